// round 1
// baseline (speedup 1.0000x reference)
#include <cuda_runtime.h>
#include <math.h>

#define NN 1000
#define FF 64
#define BB 16
#define TT 12
#define KK 5
#define CC 10
#define EE 16000
#define SS (BB*TT)          /* 192 snapshots */
#define RR (SS*NN)          /* 192000 rows   */
#define KDIM 576            /* 9 terms * 64  */
#define GDIM 128            /* 2 gates * 64  */
#define PERB (TT*NN*FF)     /* 768000        */
#define NCHUNK 1500
#define CHSZ 512

// ---------------- scratch (static device globals; no runtime alloc) ----------
__device__ float g_TX[RR * KDIM];        // 442 MB: 9 Chebyshev term blocks
__device__ float g_GZ[RR * GDIM];        // 98 MB: gate logits (z | h)
__device__ float g_HLN[RR * FF];         // 49 MB: layernormed hidden
__device__ float g_Wcat[KDIM * GDIM];    // fused weight matrix
__device__ int   g_deg_out[NN], g_deg_in[NN];
__device__ float g_inv_out[NN], g_inv_in[NN];
__device__ int   g_in_ptr[NN + 1], g_out_ptr[NN + 1];
__device__ int   g_in_idx[EE], g_out_idx[EE];
__device__ float g_in_w[EE];
__device__ int   g_cnt_in[NN], g_cnt_out[NN];
__device__ float g_part[NCHUNK * 160];

// ---------------- graph preprocessing ----------------------------------------
__global__ void k_zero() {
    int i = blockIdx.x * blockDim.x + threadIdx.x;
    if (i < NN) { g_deg_out[i] = 0; g_deg_in[i] = 0; g_cnt_in[i] = 0; g_cnt_out[i] = 0; }
}

__global__ void k_count(const int* __restrict__ ei) {
    int e = blockIdx.x * blockDim.x + threadIdx.x;
    if (e < EE) {
        atomicAdd(&g_deg_out[ei[e]], 1);       // src
        atomicAdd(&g_deg_in[ei[EE + e]], 1);   // dst
    }
}

__global__ void k_scan() {
    if (threadIdx.x == 0 && blockIdx.x == 0) {
        int a = 0, b = 0;
        for (int n = 0; n < NN; n++) {
            g_in_ptr[n] = a;  g_out_ptr[n] = b;
            a += g_deg_in[n]; b += g_deg_out[n];
            g_inv_out[n] = 1.0f / (float)g_deg_out[n];
            g_inv_in[n]  = 1.0f / (float)g_deg_in[n];
        }
        g_in_ptr[NN] = a; g_out_ptr[NN] = b;
    }
}

__global__ void k_fill(const int* __restrict__ ei) {
    int e = blockIdx.x * blockDim.x + threadIdx.x;
    if (e < EE) {
        int s = ei[e], d = ei[EE + e];
        int p = atomicAdd(&g_cnt_in[d], 1);
        g_in_idx[g_in_ptr[d] + p] = s;
        g_in_w[g_in_ptr[d] + p]  = g_inv_out[s];
        int q = atomicAdd(&g_cnt_out[s], 1);
        g_out_idx[g_out_ptr[s] + q] = d;
    }
}

// ---------------- fused weight build ------------------------------------------
// Wcat[(term*64 + ic)][gate*64 + oc]
// term 0 -> W[0,0]+W[1,0] (shared Tx0), terms 1..4 -> W[0,k], terms 5..8 -> W[1,k]
// W layout: (2, K, 2F, F): idx = ((dir*KK + k)*2*FF + ic)*FF + oc   (only ic<64 used)
__global__ void k_wcat(const float* __restrict__ Wz, const float* __restrict__ Wh) {
    int i = blockIdx.x * blockDim.x + threadIdx.x;
    if (i >= KDIM * GDIM) return;
    int col  = i % GDIM, krow = i / GDIM;
    int term = krow / FF, ic = krow % FF;
    int gate = col / FF,  oc = col % FF;
    const float* W = (gate == 0) ? Wz : Wh;
    float v;
    if (term == 0)
        v = W[((0 * KK + 0) * 2 * FF + ic) * FF + oc] +
            W[((1 * KK + 0) * 2 * FF + ic) * FF + oc];
    else if (term <= 4)
        v = W[((0 * KK + term) * 2 * FF + ic) * FF + oc];
    else
        v = W[((1 * KK + (term - 4)) * 2 * FF + ic) * FF + oc];
    g_Wcat[i] = v;
}

// ---------------- Tx0 copy -----------------------------------------------------
__global__ void k_copyx(const float* __restrict__ x) {
    int i = blockIdx.x * blockDim.x + threadIdx.x;
    if (i < RR * FF / 4) {
        int r = i / (FF / 4), f4 = i % (FF / 4);
        float4 v = ((const float4*)x)[i];
        *(float4*)&g_TX[r * KDIM + f4 * 4] = v;
    }
}

// ---------------- Chebyshev propagation step ----------------------------------
// dst_o = [2*]P_out(src_o) [- TX[:,sub]] ;  dst_i = [2*]P_in(src_i) [- TX[:,sub]]
// (sub column is SHARED between directions: reference rebinds Tx0 = Tx1o)
__global__ void k_cheb(int so, int si, int dro, int dri, int sub) {
    int row = blockIdx.x * 4 + threadIdx.y;
    if (row >= RR) return;
    int f    = threadIdx.x;                 // 0..63
    int node = row % NN;
    int sb   = (row - node) * KDIM;         // snapshot base
    int rb   = row * KDIM;

    float acc_o = 0.f;
    int jb = g_in_ptr[node], je = g_in_ptr[node + 1];
    for (int j = jb; j < je; j++)
        acc_o += g_in_w[j] * g_TX[sb + g_in_idx[j] * KDIM + so * FF + f];

    float acc_i = 0.f;
    jb = g_out_ptr[node]; je = g_out_ptr[node + 1];
    for (int j = jb; j < je; j++)
        acc_i += g_TX[sb + g_out_idx[j] * KDIM + si * FF + f];
    acc_i *= g_inv_in[node];

    if (sub >= 0) {
        float t0 = g_TX[rb + sub * FF + f];
        acc_o = 2.f * acc_o - t0;
        acc_i = 2.f * acc_i - t0;
    }
    g_TX[rb + dro * FF + f] = acc_o;
    g_TX[rb + dri * FF + f] = acc_i;
}

// ---------------- main GEMM: [RR,576] @ [576,128] -> GZ -----------------------
__global__ void __launch_bounds__(256) k_gemm() {
    __shared__ float As[8][128];
    __shared__ float Bs[8][128];
    int bm  = blockIdx.x * 128;
    int tid = threadIdx.x;
    int tr  = tid >> 4, tc = tid & 15;          // 16x16 thread grid, 8x8 micro
    int ar  = tid >> 1, ak = (tid & 1) * 4;     // A loader
    int bk  = tid >> 5, bc = (tid & 31) * 4;    // B loader

    float acc[8][8];
#pragma unroll
    for (int i = 0; i < 8; i++)
#pragma unroll
        for (int j = 0; j < 8; j++) acc[i][j] = 0.f;

    for (int k0 = 0; k0 < KDIM; k0 += 8) {
        float4 av = *(const float4*)&g_TX[(bm + ar) * KDIM + k0 + ak];
        As[ak + 0][ar] = av.x; As[ak + 1][ar] = av.y;
        As[ak + 2][ar] = av.z; As[ak + 3][ar] = av.w;
        *(float4*)&Bs[bk][bc] = *(const float4*)&g_Wcat[(k0 + bk) * GDIM + bc];
        __syncthreads();
#pragma unroll
        for (int kk = 0; kk < 8; kk++) {
            float4 a0 = *(float4*)&As[kk][tr * 8];
            float4 a1 = *(float4*)&As[kk][tr * 8 + 4];
            float4 b0 = *(float4*)&Bs[kk][tc * 8];
            float4 b1 = *(float4*)&Bs[kk][tc * 8 + 4];
            float a[8] = {a0.x,a0.y,a0.z,a0.w,a1.x,a1.y,a1.z,a1.w};
            float b[8] = {b0.x,b0.y,b0.z,b0.w,b1.x,b1.y,b1.z,b1.w};
#pragma unroll
            for (int i = 0; i < 8; i++)
#pragma unroll
                for (int j = 0; j < 8; j++) acc[i][j] += a[i] * b[j];
        }
        __syncthreads();
    }
    int orow = bm + tr * 8, ocol = tc * 8;
#pragma unroll
    for (int i = 0; i < 8; i++) {
        *(float4*)&g_GZ[(orow + i) * GDIM + ocol]     = make_float4(acc[i][0], acc[i][1], acc[i][2], acc[i][3]);
        *(float4*)&g_GZ[(orow + i) * GDIM + ocol + 4] = make_float4(acc[i][4], acc[i][5], acc[i][6], acc[i][7]);
    }
}

// ---------------- gates + relu + layernorm ------------------------------------
__global__ void k_epi(const float* __restrict__ bz, const float* __restrict__ bh,
                      const float* __restrict__ ln_g, const float* __restrict__ ln_b) {
    int row = blockIdx.x * 8 + threadIdx.y;   // one warp per row
    if (row >= RR) return;
    int lane = threadIdx.x;
    float h[2], s = 0.f;
#pragma unroll
    for (int q = 0; q < 2; q++) {
        int f = lane + q * 32;
        float zl = g_GZ[row * GDIM + f]      + bz[f];
        float hl = g_GZ[row * GDIM + FF + f] + bh[f];
        float z  = 1.f / (1.f + expf(-zl));
        float hc = (1.f - z) * tanhf(hl);
        hc = fmaxf(hc, 0.f);                  // relu
        h[q] = hc; s += hc;
    }
#pragma unroll
    for (int o = 16; o; o >>= 1) s += __shfl_xor_sync(0xffffffffu, s, o);
    float mu = s * (1.f / 64.f);
    float v = 0.f;
#pragma unroll
    for (int q = 0; q < 2; q++) { float d = h[q] - mu; v += d * d; }
#pragma unroll
    for (int o = 16; o; o >>= 1) v += __shfl_xor_sync(0xffffffffu, v, o);
    float rstd = rsqrtf(v * (1.f / 64.f) + 1e-5f);
#pragma unroll
    for (int q = 0; q < 2; q++) {
        int f = lane + q * 32;
        g_HLN[row * FF + f] = (h[q] - mu) * rstd * ln_g[f] + ln_b[f];
    }
}

// ---------------- final linear: out[b,c] = <HLN[b,:], lin_w[c,:]> + lin_b -----
__global__ void k_lin1(const float* __restrict__ w) {
    int chunk = blockIdx.x;
    int tid = threadIdx.x;            // 160 threads: (b,c) pairs
    int b = tid / CC, c = tid % CC;
    const float4* hp = (const float4*)(g_HLN + b * PERB + chunk * CHSZ);
    const float4* wp = (const float4*)(w     + c * PERB + chunk * CHSZ);
    float acc = 0.f;
#pragma unroll 4
    for (int i = 0; i < CHSZ / 4; i++) {
        float4 hv = hp[i], wv = wp[i];
        acc += hv.x * wv.x + hv.y * wv.y + hv.z * wv.z + hv.w * wv.w;
    }
    g_part[chunk * 160 + tid] = acc;
}

__global__ void k_lin2(const float* __restrict__ lb, float* __restrict__ out) {
    int tid = threadIdx.x;
    if (tid < 160) {
        float acc = 0.f;
        for (int ch = 0; ch < NCHUNK; ch++) acc += g_part[ch * 160 + tid];
        int b = tid / CC, c = tid % CC;
        out[b * CC + c] = acc + lb[c];
    }
}

// ---------------- launch -------------------------------------------------------
extern "C" void kernel_launch(void* const* d_in, const int* in_sizes, int n_in,
                              void* d_out, int out_size) {
    const float* x    = (const float*)d_in[0];
    const int*   ei   = (const int*)  d_in[1];
    const float* Wz   = (const float*)d_in[2];
    const float* bz   = (const float*)d_in[3];
    // d_in[4], d_in[5] (W_r, b_r) are mathematically dead (h0 == 0)
    const float* Wh   = (const float*)d_in[6];
    const float* bh   = (const float*)d_in[7];
    const float* lng  = (const float*)d_in[8];
    const float* lnb  = (const float*)d_in[9];
    const float* lw   = (const float*)d_in[10];
    const float* lb   = (const float*)d_in[11];
    float* out = (float*)d_out;

    k_zero<<<4, 256>>>();
    k_count<<<(EE + 255) / 256, 256>>>(ei);
    k_scan<<<1, 32>>>();
    k_fill<<<(EE + 255) / 256, 256>>>(ei);
    k_wcat<<<(KDIM * GDIM + 255) / 256, 256>>>(Wz, Wh);
    k_copyx<<<(RR * FF / 4 + 255) / 256, 256>>>(x);

    dim3 cb(64, 4);
    int cg = RR / 4;
    k_cheb<<<cg, cb>>>(0, 0, 1, 5, -1);   // Tx1o, Tx1i
    k_cheb<<<cg, cb>>>(1, 5, 2, 6, 0);    // Tx2o, Tx2i  (sub Tx0)
    k_cheb<<<cg, cb>>>(2, 6, 3, 7, 1);    // Tx3o, Tx3i  (sub Tx1o)
    k_cheb<<<cg, cb>>>(3, 7, 4, 8, 2);    // Tx4o, Tx4i  (sub Tx2o)

    k_gemm<<<RR / 128, 256>>>();

    dim3 eb(32, 8);
    k_epi<<<RR / 8, eb>>>(bz, bh, lng, lnb);

    k_lin1<<<NCHUNK, 160>>>(lw);
    k_lin2<<<1, 192>>>(lb, out);
}

// round 4
// speedup vs baseline: 1.1417x; 1.1417x over previous
#include <cuda_runtime.h>
#include <math.h>
#include <cstdint>

#define NN 1000
#define FF 64
#define BB 16
#define TT 12
#define KK 5
#define CC 10
#define EE 16000
#define SS (BB*TT)          /* 192 snapshots */
#define RR (SS*NN)          /* 192000 rows   */
#define KDIM 576            /* 9 terms * 64  */
#define GDIM 128            /* 2 gates * 64  */
#define PERB (TT*NN*FF)     /* 768000        */
#define NCHUNK 1500
#define CHSZ 512

// GEMM tiling
#define KC    48            /* K per chunk        */
#define NCH   12            /* 576 / 48 chunks    */
#define KS_PC 6             /* k-steps (of 8) per chunk */

// ---------------- scratch (static device globals; no runtime alloc) ----------
__device__ float g_TX[RR * KDIM];        // 442 MB: 9 Chebyshev term blocks
__device__ float g_HLN[RR * FF];         // 49 MB: layernormed hidden
__device__ float g_Wt[GDIM * KDIM];      // fused weights, transposed: [128 out][576 k]
__device__ int   g_deg_out[NN], g_deg_in[NN];
__device__ float g_inv_out[NN], g_inv_in[NN];
__device__ int   g_in_ptr[NN + 1], g_out_ptr[NN + 1];
__device__ int   g_in_idx[EE], g_out_idx[EE];
__device__ float g_in_w[EE];
__device__ int   g_cnt_in[NN], g_cnt_out[NN];
__device__ float g_part[NCHUNK * 160];

// ---------------- graph preprocessing ----------------------------------------
__global__ void k_zero() {
    int i = blockIdx.x * blockDim.x + threadIdx.x;
    if (i < NN) { g_deg_out[i] = 0; g_deg_in[i] = 0; g_cnt_in[i] = 0; g_cnt_out[i] = 0; }
}
__global__ void k_count(const int* __restrict__ ei) {
    int e = blockIdx.x * blockDim.x + threadIdx.x;
    if (e < EE) {
        atomicAdd(&g_deg_out[ei[e]], 1);
        atomicAdd(&g_deg_in[ei[EE + e]], 1);
    }
}
__global__ void k_scan() {
    if (threadIdx.x == 0 && blockIdx.x == 0) {
        int a = 0, b = 0;
        for (int n = 0; n < NN; n++) {
            g_in_ptr[n] = a;  g_out_ptr[n] = b;
            a += g_deg_in[n]; b += g_deg_out[n];
            g_inv_out[n] = 1.0f / (float)g_deg_out[n];
            g_inv_in[n]  = 1.0f / (float)g_deg_in[n];
        }
        g_in_ptr[NN] = a; g_out_ptr[NN] = b;
    }
}
__global__ void k_fill(const int* __restrict__ ei) {
    int e = blockIdx.x * blockDim.x + threadIdx.x;
    if (e < EE) {
        int s = ei[e], d = ei[EE + e];
        int p = atomicAdd(&g_cnt_in[d], 1);
        g_in_idx[g_in_ptr[d] + p] = s;
        g_in_w[g_in_ptr[d] + p]  = g_inv_out[s];
        int q = atomicAdd(&g_cnt_out[s], 1);
        g_out_idx[g_out_ptr[s] + q] = d;
    }
}

// ---------------- fused weight build (transposed: g_Wt[n][k]) -----------------
// col = gate*64+oc; term 0 -> W[0,0]+W[1,0]; terms 1..4 -> W[0,k]; 5..8 -> W[1,k]
__global__ void k_wcat(const float* __restrict__ Wz, const float* __restrict__ Wh) {
    int i = blockIdx.x * blockDim.x + threadIdx.x;
    if (i >= KDIM * GDIM) return;
    int col  = i / KDIM, krow = i % KDIM;
    int term = krow / FF, ic = krow % FF;
    int gate = col / FF,  oc = col % FF;
    const float* W = (gate == 0) ? Wz : Wh;
    float v;
    if (term == 0)
        v = W[((0 * KK + 0) * 2 * FF + ic) * FF + oc] +
            W[((1 * KK + 0) * 2 * FF + ic) * FF + oc];
    else if (term <= 4)
        v = W[((0 * KK + term) * 2 * FF + ic) * FF + oc];
    else
        v = W[((1 * KK + (term - 4)) * 2 * FF + ic) * FF + oc];
    g_Wt[col * KDIM + krow] = v;
}

// ---------------- Tx0 copy -----------------------------------------------------
__global__ void k_copyx(const float* __restrict__ x) {
    int i = blockIdx.x * blockDim.x + threadIdx.x;
    if (i < RR * FF / 4) {
        int r = i / (FF / 4), f4 = i % (FF / 4);
        float4 v = ((const float4*)x)[i];
        *(float4*)&g_TX[r * KDIM + f4 * 4] = v;
    }
}

// ---------------- Chebyshev propagation step ----------------------------------
__global__ void k_cheb(int so, int si, int dro, int dri, int sub) {
    int row = blockIdx.x * 4 + threadIdx.y;
    if (row >= RR) return;
    int f    = threadIdx.x;
    int node = row % NN;
    int sb   = (row - node) * KDIM;
    int rb   = row * KDIM;

    float acc_o = 0.f;
    int jb = g_in_ptr[node], je = g_in_ptr[node + 1];
    for (int j = jb; j < je; j++)
        acc_o += g_in_w[j] * g_TX[sb + g_in_idx[j] * KDIM + so * FF + f];

    float acc_i = 0.f;
    jb = g_out_ptr[node]; je = g_out_ptr[node + 1];
    for (int j = jb; j < je; j++)
        acc_i += g_TX[sb + g_out_idx[j] * KDIM + si * FF + f];
    acc_i *= g_inv_in[node];

    if (sub >= 0) {
        float t0 = g_TX[rb + sub * FF + f];
        acc_o = 2.f * acc_o - t0;
        acc_i = 2.f * acc_i - t0;
    }
    g_TX[rb + dro * FF + f] = acc_o;
    g_TX[rb + dri * FF + f] = acc_i;
}

// ================= tf32 warp-MMA GEMM [RR,576]@[576,128] + fused epilogue =====
__device__ __forceinline__ uint32_t f2tf32(float f) {
    uint32_t r; asm("cvt.rna.tf32.f32 %0, %1;" : "=r"(r) : "f"(f)); return r;
}
#define MMA_TF32(c, a0, a1, a2, a3, b0, b1) \
    asm volatile("mma.sync.aligned.m16n8k8.row.col.f32.tf32.tf32.f32 " \
        "{%0,%1,%2,%3}, {%4,%5,%6,%7}, {%8,%9}, {%0,%1,%2,%3};" \
        : "+f"((c)[0]), "+f"((c)[1]), "+f"((c)[2]), "+f"((c)[3]) \
        : "r"(a0), "r"(a1), "r"(a2), "r"(a3), "r"(b0), "r"(b1))

// smem: sA [8 mt][6 ks][32 lane][4]   (6144 floats)
//       sB [16 nt][6 ks][32 lane][2]  (6144 floats)  -> total 48 KB
__global__ void __launch_bounds__(256, 1) k_gemm_mma(
    const float* __restrict__ bz, const float* __restrict__ bh,
    const float* __restrict__ lng, const float* __restrict__ lnb)
{
    extern __shared__ float sm[];
    float* sA = sm;
    float* sB = sm + 8 * KS_PC * 32 * 4;
    const int tid = threadIdx.x, wid = tid >> 5, lane = tid & 31;
    const int row0 = blockIdx.x * 128;

    float acc[16][4];
#pragma unroll
    for (int nt = 0; nt < 16; nt++)
#pragma unroll
        for (int j = 0; j < 4; j++) acc[nt][j] = 0.f;

    // staging: thread -> row rr, half hh; 6 float4 per matrix
    const int rr = tid >> 1, hh = tid & 1;
    const float* Ag = g_TX + (size_t)(row0 + rr) * KDIM + hh * 24;
    const float* Bg = g_Wt + (size_t)rr * KDIM + hh * 24;
    float4 pa[6], pb[6];

#pragma unroll
    for (int i = 0; i < 6; i++) {          // prefetch chunk 0
        pa[i] = *(const float4*)(Ag + i * 4);
        pb[i] = *(const float4*)(Bg + i * 4);
    }

    // scatter constants
    const int mt = rr >> 4, ri = rr & 15;          // A side
    const int ntb = rr >> 3, ni = rr & 7;          // B side

#pragma unroll 1
    for (int c = 0; c < NCH; c++) {
        // ---- store permuted tf32 tiles ----
#pragma unroll
        for (int i = 0; i < 6; i++) {
            int c4 = hh * 6 + i;
            int ks = c4 >> 1, jh = c4 & 1;
            float va[4] = {pa[i].x, pa[i].y, pa[i].z, pa[i].w};
            float vb[4] = {pb[i].x, pb[i].y, pb[i].z, pb[i].w};
#pragma unroll
            for (int e = 0; e < 4; e++) {
                int la = (ri & 7) * 4 + e;
                int ja = (jh << 1) | (ri >> 3);
                ((uint32_t*)sA)[((mt * KS_PC + ks) * 32 + la) * 4 + ja] = f2tf32(va[e]);
                int lb = ni * 4 + e;
                ((uint32_t*)sB)[((ntb * KS_PC + ks) * 32 + lb) * 2 + jh] = f2tf32(vb[e]);
            }
        }
        __syncthreads();
        if (c + 1 < NCH) {
#pragma unroll
            for (int i = 0; i < 6; i++) {
                pa[i] = *(const float4*)(Ag + (c + 1) * KC + i * 4);
                pb[i] = *(const float4*)(Bg + (c + 1) * KC + i * 4);
            }
        }
        // ---- compute ----
#pragma unroll
        for (int ks = 0; ks < KS_PC; ks++) {
            float4 af = *(float4*)&sA[((wid * KS_PC + ks) * 32 + lane) * 4];
            uint32_t a0 = __float_as_uint(af.x), a1 = __float_as_uint(af.y);
            uint32_t a2 = __float_as_uint(af.z), a3 = __float_as_uint(af.w);
#pragma unroll
            for (int nt = 0; nt < 16; nt++) {
                float2 bf = *(float2*)&sB[((nt * KS_PC + ks) * 32 + lane) * 2];
                MMA_TF32(acc[nt], a0, a1, a2, a3,
                         __float_as_uint(bf.x), __float_as_uint(bf.y));
            }
        }
        __syncthreads();
    }

    // ---- stage bias/LN params through (now free) smem ----
    if (tid < 64) {
        sm[tid]       = bz[tid];
        sm[64 + tid]  = bh[tid];
        sm[128 + tid] = lng[tid];
        sm[192 + tid] = lnb[tid];
    }
    __syncthreads();

    // ---- fused epilogue: gates + relu + LayerNorm ----
    const int qr = lane >> 2, qc = lane & 3;
#pragma unroll
    for (int half = 0; half < 2; half++) {     // half 0: rows qr; half 1: rows qr+8
        float hc[16], s = 0.f;
#pragma unroll
        for (int nt = 0; nt < 8; nt++)
#pragma unroll
            for (int d = 0; d < 2; d++) {
                int f = nt * 8 + qc * 2 + d;
                float zl = acc[nt][half * 2 + d]     + sm[f];
                float hl = acc[nt + 8][half * 2 + d] + sm[64 + f];
                float z  = 1.f / (1.f + __expf(-zl));
                float v  = fmaxf((1.f - z) * tanhf(hl), 0.f);
                hc[nt * 2 + d] = v; s += v;
            }
        s += __shfl_xor_sync(0xffffffffu, s, 1);
        s += __shfl_xor_sync(0xffffffffu, s, 2);
        float mu = s * (1.f / 64.f), var = 0.f;
#pragma unroll
        for (int j = 0; j < 16; j++) { float d = hc[j] - mu; var += d * d; }
        var += __shfl_xor_sync(0xffffffffu, var, 1);
        var += __shfl_xor_sync(0xffffffffu, var, 2);
        float rstd = rsqrtf(var * (1.f / 64.f) + 1e-5f);
        int row = row0 + wid * 16 + qr + half * 8;
        float* op = g_HLN + (size_t)row * FF;
#pragma unroll
        for (int nt = 0; nt < 8; nt++) {
            int f0 = nt * 8 + qc * 2;
            float2 o;
            o.x = (hc[nt * 2]     - mu) * rstd * sm[128 + f0]     + sm[192 + f0];
            o.y = (hc[nt * 2 + 1] - mu) * rstd * sm[128 + f0 + 1] + sm[192 + f0 + 1];
            *(float2*)(op + f0) = o;
        }
    }
}

// ---------------- final linear: out[b,c] = <HLN[b,:], lin_w[c,:]> + lin_b -----
__global__ void k_lin1(const float* __restrict__ w) {
    int chunk = blockIdx.x;
    int tid = threadIdx.x;
    int b = tid / CC, c = tid % CC;
    const float4* hp = (const float4*)(g_HLN + b * PERB + chunk * CHSZ);
    const float4* wp = (const float4*)(w     + c * PERB + chunk * CHSZ);
    float acc = 0.f;
#pragma unroll 4
    for (int i = 0; i < CHSZ / 4; i++) {
        float4 hv = hp[i], wv = wp[i];
        acc += hv.x * wv.x + hv.y * wv.y + hv.z * wv.z + hv.w * wv.w;
    }
    g_part[chunk * 160 + tid] = acc;
}
__global__ void k_lin2(const float* __restrict__ lb, float* __restrict__ out) {
    int tid = threadIdx.x;
    if (tid < 160) {
        float acc = 0.f;
        for (int ch = 0; ch < NCHUNK; ch++) acc += g_part[ch * 160 + tid];
        int b = tid / CC, c = tid % CC;
        out[b * CC + c] = acc + lb[c];
    }
}

// ---------------- launch -------------------------------------------------------
extern "C" void kernel_launch(void* const* d_in, const int* in_sizes, int n_in,
                              void* d_out, int out_size) {
    const float* x    = (const float*)d_in[0];
    const int*   ei   = (const int*)  d_in[1];
    const float* Wz   = (const float*)d_in[2];
    const float* bz   = (const float*)d_in[3];
    // d_in[4], d_in[5] (W_r, b_r) are mathematically dead (h0 == 0)
    const float* Wh   = (const float*)d_in[6];
    const float* bh   = (const float*)d_in[7];
    const float* lng  = (const float*)d_in[8];
    const float* lnb  = (const float*)d_in[9];
    const float* lw   = (const float*)d_in[10];
    const float* lb   = (const float*)d_in[11];
    float* out = (float*)d_out;

    k_zero<<<4, 256>>>();
    k_count<<<(EE + 255) / 256, 256>>>(ei);
    k_scan<<<1, 32>>>();
    k_fill<<<(EE + 255) / 256, 256>>>(ei);
    k_wcat<<<(KDIM * GDIM + 255) / 256, 256>>>(Wz, Wh);
    k_copyx<<<(RR * FF / 4 + 255) / 256, 256>>>(x);

    dim3 cb(64, 4);
    int cg = RR / 4;
    k_cheb<<<cg, cb>>>(0, 0, 1, 5, -1);   // Tx1o, Tx1i
    k_cheb<<<cg, cb>>>(1, 5, 2, 6, 0);    // Tx2o, Tx2i  (sub Tx0)
    k_cheb<<<cg, cb>>>(2, 6, 3, 7, 1);    // Tx3o, Tx3i  (sub Tx1o)
    k_cheb<<<cg, cb>>>(3, 7, 4, 8, 2);    // Tx4o, Tx4i  (sub Tx2o)

    k_gemm_mma<<<RR / 128, 256, 49152>>>(bz, bh, lng, lnb);

    k_lin1<<<NCHUNK, 160>>>(lw);
    k_lin2<<<1, 192>>>(lb, out);
}